// round 8
// baseline (speedup 1.0000x reference)
#include <cuda_runtime.h>
#include <cuda_fp16.h>
#include <math.h>
#include <stdint.h>

#define DM 1024
#define NH 16
#define DK 64
#define BB 4
#define TT 2048
#define MT (BB*TT)   // 8192 rows

// ---------------- scratch (static; allocation forbidden) ----------------
__device__ __half g_xhi[(size_t)MT * DM];
__device__ __half g_xlo[(size_t)MT * DM];
__device__ __half g_qhi[(size_t)MT * DM];
__device__ __half g_qlo[(size_t)MT * DM];
__device__ __half g_khi[(size_t)MT * DM];
__device__ __half g_vhi[(size_t)MT * DM];
__device__ __half g_vlo[(size_t)MT * DM];
__device__ __half g_ahi[(size_t)MT * DM];
__device__ __half g_alo[(size_t)MT * DM];
__device__ __half g_whi[(size_t)4 * DM * DM];

// ---------------- helpers ----------------
__device__ __forceinline__ uint32_t smem_u32(const void* p) {
    uint32_t a;
    asm("{ .reg .u64 t; cvta.to.shared.u64 t, %1; cvt.u32.u64 %0, t; }" : "=r"(a) : "l"(p));
    return a;
}
__device__ __forceinline__ void cp16(uint32_t dst, const void* src) {
    asm volatile("cp.async.cg.shared.global [%0], [%1], 16;" :: "r"(dst), "l"(src));
}
__device__ __forceinline__ void ldsm4(uint32_t* r, uint32_t addr) {
    asm volatile("ldmatrix.sync.aligned.m8n8.x4.shared.b16 {%0,%1,%2,%3}, [%4];"
                 : "=r"(r[0]), "=r"(r[1]), "=r"(r[2]), "=r"(r[3]) : "r"(addr));
}
__device__ __forceinline__ void ldsm4t(uint32_t* r, uint32_t addr) {
    asm volatile("ldmatrix.sync.aligned.m8n8.x4.trans.shared.b16 {%0,%1,%2,%3}, [%4];"
                 : "=r"(r[0]), "=r"(r[1]), "=r"(r[2]), "=r"(r[3]) : "r"(addr));
}
__device__ __forceinline__ void mma16816(float* c, const uint32_t* a, const uint32_t* b) {
    asm volatile("mma.sync.aligned.m16n8k16.row.col.f32.f16.f16.f32 "
                 "{%0,%1,%2,%3}, {%4,%5,%6,%7}, {%8,%9}, {%0,%1,%2,%3};"
                 : "+f"(c[0]), "+f"(c[1]), "+f"(c[2]), "+f"(c[3])
                 : "r"(a[0]), "r"(a[1]), "r"(a[2]), "r"(a[3]), "r"(b[0]), "r"(b[1]));
}
__device__ __forceinline__ uint32_t packh2(float x, float y) {
    __half2 t = __floats2half2_rn(x, y);   // low = x
    return *(uint32_t*)&t;
}
__device__ __forceinline__ void split_pair(float x, float y, uint32_t& hi, uint32_t& lo) {
    hi = packh2(x, y);
    __half2 hv = *(__half2*)&hi;
    lo = packh2(x - __low2float(hv), y - __high2float(hv));
}

// ---------------- fp32 -> fp16 converters ----------------
__global__ __launch_bounds__(256) void cvt2_kernel(const float* __restrict__ x,
                                                   __half* __restrict__ hi,
                                                   __half* __restrict__ lo, int n4)
{
    int i = blockIdx.x * 256 + threadIdx.x;
    if (i >= n4) return;
    float4 v = ((const float4*)x)[i];
    uint32_t h0, l0, h1, l1;
    split_pair(v.x, v.y, h0, l0);
    split_pair(v.z, v.w, h1, l1);
    uint32_t* hp = (uint32_t*)(hi + (size_t)i * 4);
    uint32_t* lp = (uint32_t*)(lo + (size_t)i * 4);
    hp[0] = h0; hp[1] = h1;
    lp[0] = l0; lp[1] = l1;
}

__global__ __launch_bounds__(256) void cvtw_kernel(const float* __restrict__ w0,
                                                   const float* __restrict__ w1,
                                                   const float* __restrict__ w2,
                                                   const float* __restrict__ w3,
                                                   __half* __restrict__ hi, int n4)
{
    int i = blockIdx.x * 256 + threadIdx.x;
    if (i >= n4) return;
    const float* src = (blockIdx.z == 0) ? w0 : (blockIdx.z == 1) ? w1 :
                       (blockIdx.z == 2) ? w2 : w3;
    float4 v = ((const float4*)src)[i];
    uint32_t* hp = (uint32_t*)(hi + (size_t)blockIdx.z * DM * DM + (size_t)i * 4);
    hp[0] = packh2(v.x, v.y);
    hp[1] = packh2(v.z, v.w);
}

// ---------------- mma.sync GEMM: Out[M,N] = A[M,K] @ W[N,K]^T + bias ----------------
// CTA 128x256, 256 threads, 8 warps (2x4), warp tile 64x64. BK=32, 3-stage
// cp.async, one __syncthreads per chunk. acc += Ahi*Whi + Alo*Whi.
#define BKc 32
#define BKP 40
#define MAT_A (128 * BKP * 2)      // 10240
#define MAT_Bt (256 * BKP * 2)     // 20480
#define STAGE_B (2 * MAT_A + MAT_Bt)   // 40960
#define NSTAGE 3
#define GEMM_SMEM (NSTAGE * STAGE_B)   // 122880
#define NKCH (DM / BKc)            // 32

// OUTMODE 0: fp32 out. OUTMODE 1: fp16 hi(/lo) out, scaled; Olo may be null.
template<int OUTMODE>
__device__ __forceinline__ void gemm_mma_body(
    const __half* __restrict__ Ahi, const __half* __restrict__ Alo,
    const __half* __restrict__ Bhi,
    const float* __restrict__ bias, float* __restrict__ OutF,
    __half* __restrict__ Ohi, __half* __restrict__ Olo, float scale)
{
    extern __shared__ char smc[];
    const uint32_t sb = smem_u32(smc);
    const int tid = threadIdx.x, wid = tid >> 5, lane = tid & 31;
    const int warp_m = wid & 1, warp_n = wid >> 1;       // 2 x 4
    const int m0 = blockIdx.y * 128, n0 = blockIdx.x * 256;

    float acc[4][8][4];
#pragma unroll
    for (int i = 0; i < 4; i++)
#pragma unroll
        for (int j = 0; j < 8; j++)
#pragma unroll
            for (int k = 0; k < 4; k++) acc[i][j][k] = 0.f;

    // stage loader: Ahi 512 + Alo 512 + B 1024 cp16 = 2048, 8 per thread
    auto load_stage = [&](int c, int st) {
        const uint32_t sbase = sb + st * STAGE_B;
        const int k0 = c * BKc;
#pragma unroll
        for (int t = 0; t < 8; t++) {
            const int idx = t * 256 + tid;
            if (t < 2) {                       // Ahi: idx in [0,512)
                const int row = idx >> 2, seg = idx & 3;
                cp16(sbase + row * (BKP * 2) + seg * 16,
                     Ahi + (size_t)(m0 + row) * DM + k0 + seg * 8);
            } else if (t < 4) {                // Alo
                const int rem = idx - 512;
                const int row = rem >> 2, seg = rem & 3;
                cp16(sbase + MAT_A + row * (BKP * 2) + seg * 16,
                     Alo + (size_t)(m0 + row) * DM + k0 + seg * 8);
            } else {                           // B: rem in [0,1024)
                const int rem = idx - 1024;
                const int row = rem >> 2, seg = rem & 3;
                cp16(sbase + 2 * MAT_A + row * (BKP * 2) + seg * 16,
                     Bhi + (size_t)(n0 + row) * DM + k0 + seg * 8);
            }
        }
        asm volatile("cp.async.commit_group;");
    };

    load_stage(0, 0);
    load_stage(1, 1);

    const int arow = warp_m * 64 + (lane & 15);
    const int aseg = (lane >> 4) * 8;
    const int bn   = warp_n * 64 + ((lane >> 4) * 8) + (lane & 7);
    const int bk   = ((lane >> 3) & 1) * 8;

    for (int c = 0; c < NKCH; c++) {
        if (c + 1 < NKCH) { asm volatile("cp.async.wait_group 1;" ::: "memory"); }
        else              { asm volatile("cp.async.wait_group 0;" ::: "memory"); }
        __syncthreads();

        if (c + 2 < NKCH) load_stage(c + 2, (c + 2) % NSTAGE);

        const uint32_t sbase = sb + (c % NSTAGE) * STAGE_B;
        const uint32_t aHi = sbase;
        const uint32_t aLo = sbase + MAT_A;
        const uint32_t bBs = sbase + 2 * MAT_A;

#pragma unroll
        for (int ks = 0; ks < 2; ks++) {
            const int k0 = ks * 16;
            uint32_t ah[4][4], al[4][4];
#pragma unroll
            for (int mt = 0; mt < 4; mt++) {
                uint32_t off = ((arow + mt * 16) * BKP + k0 + aseg) * 2;
                ldsm4(ah[mt], aHi + off);
                ldsm4(al[mt], aLo + off);
            }
            uint32_t bh[4][4];
#pragma unroll
            for (int np = 0; np < 4; np++) {
                uint32_t off = ((bn + np * 16) * BKP + k0 + bk) * 2;
                ldsm4(bh[np], bBs + off);
            }
#pragma unroll
            for (int mt = 0; mt < 4; mt++)
#pragma unroll
                for (int nt = 0; nt < 8; nt++) {
                    const uint32_t* Bh = &bh[nt >> 1][(nt & 1) * 2];
                    mma16816(acc[mt][nt], ah[mt], Bh);
                    mma16816(acc[mt][nt], al[mt], Bh);
                }
        }
    }

    const int rbase = m0 + warp_m * 64 + (lane >> 2);
    const int cbase = n0 + warp_n * 64 + (lane & 3) * 2;
#pragma unroll
    for (int mt = 0; mt < 4; mt++) {
#pragma unroll
        for (int nt = 0; nt < 8; nt++) {
            const int col = cbase + nt * 8;
            const float b0 = bias[col], b1 = bias[col + 1];
            const size_t a0 = (size_t)(rbase + mt * 16) * DM + col;
            const size_t a1 = (size_t)(rbase + mt * 16 + 8) * DM + col;
            if (OUTMODE == 0) {
                OutF[a0]     = acc[mt][nt][0] + b0;
                OutF[a0 + 1] = acc[mt][nt][1] + b1;
                OutF[a1]     = acc[mt][nt][2] + b0;
                OutF[a1 + 1] = acc[mt][nt][3] + b1;
            } else {
                float v0 = (acc[mt][nt][0] + b0) * scale;
                float v1 = (acc[mt][nt][1] + b1) * scale;
                float v2 = (acc[mt][nt][2] + b0) * scale;
                float v3 = (acc[mt][nt][3] + b1) * scale;
                if (Olo) {
                    uint32_t h01, l01, h23, l23;
                    split_pair(v0, v1, h01, l01);
                    split_pair(v2, v3, h23, l23);
                    *(uint32_t*)(Ohi + a0) = h01;
                    *(uint32_t*)(Olo + a0) = l01;
                    *(uint32_t*)(Ohi + a1) = h23;
                    *(uint32_t*)(Olo + a1) = l23;
                } else {
                    *(uint32_t*)(Ohi + a0) = packh2(v0, v1);
                    *(uint32_t*)(Ohi + a1) = packh2(v2, v3);
                }
            }
        }
    }
}

__global__ __launch_bounds__(256, 1) void qkv_mma_kernel(
    const float* __restrict__ bq, const float* __restrict__ bk, const float* __restrict__ bv)
{
    const size_t wo = (size_t)blockIdx.z * DM * DM;
    const float* bias = (blockIdx.z == 0) ? bq : (blockIdx.z == 1) ? bk : bv;
    __half* Ohi = (blockIdx.z == 0) ? g_qhi : (blockIdx.z == 1) ? g_khi : g_vhi;
    __half* Olo = (blockIdx.z == 0) ? g_qlo : (blockIdx.z == 1) ? nullptr : g_vlo;
    const float scale = (blockIdx.z == 0) ? 0.125f : 1.0f;   // 1/sqrt(64), exact
    gemm_mma_body<1>(g_xhi, g_xlo, g_whi + wo, bias, nullptr, Ohi, Olo, scale);
}

__global__ __launch_bounds__(256, 1) void oproj_mma_kernel(const float* __restrict__ bo,
                                                           float* __restrict__ Out)
{
    const size_t wo = (size_t)3 * DM * DM;
    gemm_mma_body<0>(g_ahi, g_alo, g_whi + wo, bo, Out, nullptr, nullptr, 1.0f);
}

// ---------------- tensor-core flash attention ----------------
// 2 CTAs/SM: Q frags reloaded from smem per use (regs <= 128).
#define LQ 72
#define QTILE_B (128 * LQ * 2)     // 18432
#define KVTILE_B (64 * LQ * 2)     // 9216
#define STAGE_KV (3 * KVTILE_B)    // Khi, Vhi, Vlo
#define SM_QHI 0
#define SM_QLO QTILE_B
#define SM_KV0 (2 * QTILE_B)
#define ATTN_SMEM (2 * QTILE_B + 2 * STAGE_KV)   // 92160

__global__ __launch_bounds__(256, 2) void attn_kernel()
{
    extern __shared__ char smc[];
    const uint32_t sb = smem_u32(smc);
    const int qt = gridDim.x - 1 - blockIdx.x;   // longest CTAs first
    const int bh = blockIdx.y;
    const int b = bh >> 4, h = bh & 15;
    const int tid = threadIdx.x, w = tid >> 5, lane = tid & 31;
    const int q0 = qt * 128;
    const size_t tok0 = (size_t)b * TT;
    const int hoff = h * DK;

#pragma unroll
    for (int it = 0; it < 4; it++) {
        int idx = tid + it * 256;
        int row = idx >> 3, seg = idx & 7;
        size_t g = (tok0 + q0 + row) * DM + hoff + seg * 8;
        uint32_t so = (uint32_t)(row * LQ + seg * 8) * 2;
        cp16(sb + SM_QHI + so, g_qhi + g);
        cp16(sb + SM_QLO + so, g_qlo + g);
    }
    asm volatile("cp.async.commit_group;");

    auto load_kv = [&](int jb, int st) {
        const uint32_t sbase = sb + SM_KV0 + st * STAGE_KV;
#pragma unroll
        for (int it = 0; it < 2; it++) {
            int idx = tid + it * 256;
            int row = idx >> 3, seg = idx & 7;
            size_t g = (tok0 + jb * 64 + row) * DM + hoff + seg * 8;
            uint32_t so = (uint32_t)(row * LQ + seg * 8) * 2;
            cp16(sbase + so,                g_khi + g);
            cp16(sbase + KVTILE_B + so,     g_vhi + g);
            cp16(sbase + 2 * KVTILE_B + so, g_vlo + g);
        }
        asm volatile("cp.async.commit_group;");
    };

    const int nkb = 2 * qt + 2;
    load_kv(0, 0);

    float of[8][4];
#pragma unroll
    for (int i = 0; i < 8; i++)
#pragma unroll
        for (int j = 0; j < 4; j++) of[i][j] = 0.f;
    float mi0 = -INFINITY, mi1 = -INFINITY, li0 = 0.f, li1 = 0.f;

    for (int jb = 0; jb < nkb; jb++) {
        if (jb + 1 < nkb) {
            load_kv(jb + 1, (jb + 1) & 1);
            asm volatile("cp.async.wait_group 1;" ::: "memory");
        } else {
            asm volatile("cp.async.wait_group 0;" ::: "memory");
        }
        __syncthreads();

        const bool active = (jb * 64 <= q0 + 16 * w + 15);
        if (active) {
            const uint32_t kbase = sb + SM_KV0 + (jb & 1) * STAGE_KV;
            float sf[8][4];
#pragma unroll
            for (int i = 0; i < 8; i++)
#pragma unroll
                for (int j = 0; j < 4; j++) sf[i][j] = 0.f;

            // S = Q K^T (2-term: Qhi*Khi + Qlo*Khi); Q frags from smem
#pragma unroll
            for (int ks = 0; ks < 4; ks++) {
                uint32_t qh[4], ql[4];
                uint32_t qoff = (uint32_t)((16 * w + (lane & 15)) * LQ + ks * 16 + (lane >> 4) * 8) * 2;
                ldsm4(qh, sb + SM_QHI + qoff);
                ldsm4(ql, sb + SM_QLO + qoff);
                uint32_t kh[4][4];
#pragma unroll
                for (int np = 0; np < 4; np++) {
                    uint32_t off = (uint32_t)((np * 16 + (lane >> 4) * 8 + (lane & 7)) * LQ
                                              + ks * 16 + ((lane >> 3) & 1) * 8) * 2;
                    ldsm4(kh[np], kbase + off);
                }
#pragma unroll
                for (int nt = 0; nt < 8; nt++) {
                    const uint32_t* Bh = &kh[nt >> 1][(nt & 1) * 2];
                    mma16816(sf[nt], qh, Bh);
                    mma16816(sf[nt], ql, Bh);
                }
            }

            const int r0 = q0 + 16 * w + (lane >> 2), r1 = r0 + 8;
            if (jb * 64 + 63 > r0) {
#pragma unroll
                for (int nt = 0; nt < 8; nt++) {
                    int gk = jb * 64 + nt * 8 + (lane & 3) * 2;
                    if (gk     > r0) sf[nt][0] = -INFINITY;
                    if (gk + 1 > r0) sf[nt][1] = -INFINITY;
                    if (gk     > r1) sf[nt][2] = -INFINITY;
                    if (gk + 1 > r1) sf[nt][3] = -INFINITY;
                }
            }

            float mx0 = -INFINITY, mx1 = -INFINITY;
#pragma unroll
            for (int nt = 0; nt < 8; nt++) {
                mx0 = fmaxf(mx0, fmaxf(sf[nt][0], sf[nt][1]));
                mx1 = fmaxf(mx1, fmaxf(sf[nt][2], sf[nt][3]));
            }
            mx0 = fmaxf(mx0, __shfl_xor_sync(0xffffffffu, mx0, 1));
            mx0 = fmaxf(mx0, __shfl_xor_sync(0xffffffffu, mx0, 2));
            mx1 = fmaxf(mx1, __shfl_xor_sync(0xffffffffu, mx1, 1));
            mx1 = fmaxf(mx1, __shfl_xor_sync(0xffffffffu, mx1, 2));
            const float mn0 = fmaxf(mi0, mx0), mn1 = fmaxf(mi1, mx1);
            const float c0 = __expf(mi0 - mn0), c1 = __expf(mi1 - mn1);
            float rs0 = 0.f, rs1 = 0.f;
#pragma unroll
            for (int nt = 0; nt < 8; nt++) {
                sf[nt][0] = __expf(sf[nt][0] - mn0);
                sf[nt][1] = __expf(sf[nt][1] - mn0);
                sf[nt][2] = __expf(sf[nt][2] - mn1);
                sf[nt][3] = __expf(sf[nt][3] - mn1);
                rs0 += sf[nt][0] + sf[nt][1];
                rs1 += sf[nt][2] + sf[nt][3];
            }
            rs0 += __shfl_xor_sync(0xffffffffu, rs0, 1);
            rs0 += __shfl_xor_sync(0xffffffffu, rs0, 2);
            rs1 += __shfl_xor_sync(0xffffffffu, rs1, 1);
            rs1 += __shfl_xor_sync(0xffffffffu, rs1, 2);
            li0 = li0 * c0 + rs0; li1 = li1 * c1 + rs1;
            mi0 = mn0; mi1 = mn1;
#pragma unroll
            for (int nt = 0; nt < 8; nt++) {
                of[nt][0] *= c0; of[nt][1] *= c0;
                of[nt][2] *= c1; of[nt][3] *= c1;
            }

            const uint32_t vbase = kbase + KVTILE_B;
#pragma unroll
            for (int ks = 0; ks < 4; ks++) {
                uint32_t ph[4];
                ph[0] = packh2(sf[2 * ks][0],     sf[2 * ks][1]);
                ph[1] = packh2(sf[2 * ks][2],     sf[2 * ks][3]);
                ph[2] = packh2(sf[2 * ks + 1][0], sf[2 * ks + 1][1]);
                ph[3] = packh2(sf[2 * ks + 1][2], sf[2 * ks + 1][3]);
                uint32_t vh[4][4], vl[4][4];
#pragma unroll
                for (int np = 0; np < 4; np++) {
                    uint32_t off = (uint32_t)((ks * 16 + ((lane >> 3) & 1) * 8 + (lane & 7)) * LQ
                                              + np * 16 + (lane >> 4) * 8) * 2;
                    ldsm4t(vh[np], vbase + off);
                    ldsm4t(vl[np], vbase + KVTILE_B + off);
                }
#pragma unroll
                for (int nt = 0; nt < 8; nt++) {
                    const uint32_t* Bh = &vh[nt >> 1][(nt & 1) * 2];
                    const uint32_t* Bl = &vl[nt >> 1][(nt & 1) * 2];
                    mma16816(of[nt], ph, Bh);
                    mma16816(of[nt], ph, Bl);
                }
            }
        }
        __syncthreads();
    }

    const float inv0 = 1.f / li0, inv1 = 1.f / li1;
    const int trow = q0 + 16 * w + (lane >> 2);
#pragma unroll
    for (int nt = 0; nt < 8; nt++) {
        const int col = hoff + nt * 8 + (lane & 3) * 2;
        float v0 = of[nt][0] * inv0, v1 = of[nt][1] * inv0;
        float v2 = of[nt][2] * inv1, v3 = of[nt][3] * inv1;
        uint32_t h01, l01, h23, l23;
        split_pair(v0, v1, h01, l01);
        split_pair(v2, v3, h23, l23);
        const size_t a0 = (tok0 + trow) * DM + col;
        const size_t a1 = (tok0 + trow + 8) * DM + col;
        *(uint32_t*)(g_ahi + a0) = h01;
        *(uint32_t*)(g_alo + a0) = l01;
        *(uint32_t*)(g_ahi + a1) = h23;
        *(uint32_t*)(g_alo + a1) = l23;
    }
}

// ----------------------------------------------------------------------------
extern "C" void kernel_launch(void* const* d_in, const int* in_sizes, int n_in,
                              void* d_out, int out_size)
{
    const float* q  = (const float*)d_in[0];
    const float* Wq = (const float*)d_in[2];
    const float* bq = (const float*)d_in[3];
    const float* Wk = (const float*)d_in[4];
    const float* bk = (const float*)d_in[5];
    const float* Wv = (const float*)d_in[6];
    const float* bv = (const float*)d_in[7];
    const float* Wo = (const float*)d_in[8];
    const float* bo = (const float*)d_in[9];
    float* out = (float*)d_out;

    cudaFuncSetAttribute(qkv_mma_kernel, cudaFuncAttributeMaxDynamicSharedMemorySize, GEMM_SMEM);
    cudaFuncSetAttribute(oproj_mma_kernel, cudaFuncAttributeMaxDynamicSharedMemorySize, GEMM_SMEM);
    cudaFuncSetAttribute(attn_kernel, cudaFuncAttributeMaxDynamicSharedMemorySize, ATTN_SMEM);

    __half *whi, *xhi, *xlo;
    cudaGetSymbolAddress((void**)&whi, g_whi);
    cudaGetSymbolAddress((void**)&xhi, g_xhi);
    cudaGetSymbolAddress((void**)&xlo, g_xlo);

    const int nX4 = MT * DM / 4, nW4 = DM * DM / 4;
    cvt2_kernel<<<(nX4 + 255) / 256, 256>>>(q, xhi, xlo, nX4);
    dim3 gw((nW4 + 255) / 256, 1, 4);
    cvtw_kernel<<<gw, 256>>>(Wq, Wk, Wv, Wo, whi, nW4);

    dim3 gq(DM / 256, MT / 128, 3);
    qkv_mma_kernel<<<gq, 256, GEMM_SMEM>>>(bq, bk, bv);

    dim3 ga(TT / 128, BB * NH);
    attn_kernel<<<ga, 256, ATTN_SMEM>>>();

    dim3 go(DM / 256, MT / 128, 1);
    oproj_mma_kernel<<<go, 256, GEMM_SMEM>>>(bo, out);
}